// round 1
// baseline (speedup 1.0000x reference)
#include <cuda_runtime.h>
#include <cuda_bf16.h>
#include <math.h>

// Problem constants
#define BB   4
#define LL   2048
#define DD   2048
#define HH   16
#define HD   128
#define MM   (BB * LL)       // 8192

// ---------------------------------------------------------------------------
// Scratch (device globals; no allocation allowed)
// ---------------------------------------------------------------------------
__device__ float g_q[(size_t)MM * DD];
__device__ float g_k[(size_t)MM * DD];
__device__ float g_v[(size_t)MM * DD];
__device__ float g_attn[(size_t)MM * DD];
__device__ float g_cos[LL * (HD / 2)];
__device__ float g_sin[LL * (HD / 2)];

// ---------------------------------------------------------------------------
// RoPE tables: cos/sin of t * 10000^(-i/64), computed in double for accuracy
// ---------------------------------------------------------------------------
__global__ void rope_tables_kernel() {
    int t = blockIdx.x;       // 0..2047
    int i = threadIdx.x;      // 0..63
    double inv = exp(-log(10000.0) * ((double)i / 64.0));
    float invf = (float)inv;
    float freq = (float)t * invf;           // match fp32 outer product
    double ph = (double)freq;
    g_cos[t * 64 + i] = (float)cos(ph);
    g_sin[t * 64 + i] = (float)sin(ph);
}

// ---------------------------------------------------------------------------
// FFMA GEMM: C[M,N] = A[M,K] @ B[K,N], row-major. 128x128x8 tiles, 256 thr,
// 8x8 per-thread microtile, double-buffered smem.
// ---------------------------------------------------------------------------
#define GBM 128
#define GBN 128
#define GBK 8

__global__ __launch_bounds__(256) void gemm_ffma(
    const float* __restrict__ A, const float* __restrict__ B,
    float* __restrict__ C, int M, int N, int K)
{
    __shared__ float sA[2][GBK][GBM];
    __shared__ float sB[2][GBK][GBN];

    const int tid = threadIdx.x;
    const int bm = blockIdx.y * GBM;
    const int bn = blockIdx.x * GBN;

    const int rowBase = (tid >> 4) * 8;   // 0..120
    const int colBase = (tid & 15) * 8;   // 0..120

    const int aRow = tid >> 1;            // 0..127
    const int aCol = (tid & 1) * 4;       // 0 or 4
    const int bRow = tid >> 5;            // 0..7
    const int bCol = (tid & 31) * 4;      // 0..124

    const float* Aptr = A + (size_t)(bm + aRow) * K + aCol;
    const float* Bptr = B + (size_t)bRow * N + bn + bCol;

    float acc[8][8];
#pragma unroll
    for (int i = 0; i < 8; ++i)
#pragma unroll
        for (int j = 0; j < 8; ++j) acc[i][j] = 0.f;

    // prologue: stage 0
    float4 ra = *(const float4*)(Aptr);
    float4 rb = *(const float4*)(Bptr);
    sA[0][aCol + 0][aRow] = ra.x;
    sA[0][aCol + 1][aRow] = ra.y;
    sA[0][aCol + 2][aRow] = ra.z;
    sA[0][aCol + 3][aRow] = ra.w;
    *(float4*)&sB[0][bRow][bCol] = rb;
    __syncthreads();

    const int nStages = K / GBK;
    for (int s = 0; s < nStages; ++s) {
        const int cur = s & 1;
        const int nxt = cur ^ 1;
        if (s + 1 < nStages) {
            ra = *(const float4*)(Aptr + (size_t)(s + 1) * GBK);
            rb = *(const float4*)(Bptr + (size_t)(s + 1) * GBK * N);
        }
#pragma unroll
        for (int kk = 0; kk < GBK; ++kk) {
            float a[8], b[8];
            *(float4*)&a[0] = *(float4*)&sA[cur][kk][rowBase];
            *(float4*)&a[4] = *(float4*)&sA[cur][kk][rowBase + 4];
            *(float4*)&b[0] = *(float4*)&sB[cur][kk][colBase];
            *(float4*)&b[4] = *(float4*)&sB[cur][kk][colBase + 4];
#pragma unroll
            for (int i = 0; i < 8; ++i)
#pragma unroll
                for (int j = 0; j < 8; ++j)
                    acc[i][j] += a[i] * b[j];
        }
        if (s + 1 < nStages) {
            sA[nxt][aCol + 0][aRow] = ra.x;
            sA[nxt][aCol + 1][aRow] = ra.y;
            sA[nxt][aCol + 2][aRow] = ra.z;
            sA[nxt][aCol + 3][aRow] = ra.w;
            *(float4*)&sB[nxt][bRow][bCol] = rb;
        }
        __syncthreads();
    }

#pragma unroll
    for (int i = 0; i < 8; ++i) {
        float4 o0 = make_float4(acc[i][0], acc[i][1], acc[i][2], acc[i][3]);
        float4 o1 = make_float4(acc[i][4], acc[i][5], acc[i][6], acc[i][7]);
        float* crow = C + (size_t)(bm + rowBase + i) * N + bn + colBase;
        *(float4*)(crow) = o0;
        *(float4*)(crow + 4) = o1;
    }
}

// ---------------------------------------------------------------------------
// RoPE apply, in-place on q and k (layout [B,L,H,HD])
// ---------------------------------------------------------------------------
__global__ void rope_apply_kernel(float* __restrict__ q, float* __restrict__ k) {
    const size_t n = (size_t)BB * LL * HH * 64;
    size_t idx = (size_t)blockIdx.x * blockDim.x + threadIdx.x;
    float* p = q;
    size_t e = idx;
    if (e >= n) { p = k; e -= n; }
    int i = (int)(e & 63);
    size_t rest = e >> 6;       // b*L*H + l*H + h
    int h = (int)(rest & 15);
    size_t bl = rest >> 4;      // b*L + l
    int l = (int)(bl & (LL - 1));
    size_t base = bl * DD + (size_t)h * HD;
    float c = g_cos[l * 64 + i];
    float s = g_sin[l * 64 + i];
    float x1 = p[base + i];
    float x2 = p[base + i + 64];
    p[base + i]      = x1 * c - x2 * s;
    p[base + i + 64] = x2 * c + x1 * s;
}

// ---------------------------------------------------------------------------
// Flash attention, causal. Q/K/V in [B,L,H,HD] fp32.
// Tile: 64 q-rows x 64 k-cols, Hd=128. 256 threads (16x16), thread owns
// 4x4 of S and 4 rows x 8 dims of O.
// ---------------------------------------------------------------------------
#define FBM 64
#define FBN 64
#define SQ_LD 132
#define SKT_LD 68
#define SV_LD 132
#define SP_LD 68
#define FLASH_SMEM_FLOATS (FBM*SQ_LD + HD*SKT_LD + FBN*SV_LD + FBM*SP_LD)
#define FLASH_SMEM_BYTES (FLASH_SMEM_FLOATS * 4)

__global__ __launch_bounds__(256, 1) void flash_attn_kernel(
    const float* __restrict__ Q, const float* __restrict__ K,
    const float* __restrict__ V, float* __restrict__ O)
{
    extern __shared__ float sm[];
    float* sQ  = sm;                          // [64][132]
    float* sKt = sQ + FBM * SQ_LD;            // [128][68]  (k-major)
    float* sV  = sKt + HD * SKT_LD;           // [64][132]
    float* sP  = sV + FBN * SV_LD;            // [64][68]

    const int tid = threadIdx.x;
    const int tx = tid & 15;
    const int ty = tid >> 4;
    const int b = blockIdx.y >> 4;
    const int h = blockIdx.y & 15;
    const int q0 = blockIdx.x * FBM;
    const float scale = 0.08838834764831845f;   // 1/sqrt(128)

    const size_t bOff = (size_t)b * LL * DD;
    const size_t hOff = (size_t)h * HD;

    // Load Q tile (pre-scaled)
#pragma unroll
    for (int it = 0; it < 8; ++it) {
        int e = tid * 4 + it * 1024;
        int r = e >> 7, c = e & 127;
        float4 v = *(const float4*)(Q + bOff + (size_t)(q0 + r) * DD + hOff + c);
        v.x *= scale; v.y *= scale; v.z *= scale; v.w *= scale;
        *(float4*)&sQ[r * SQ_LD + c] = v;
    }

    float mrow[4], lrow[4], oacc[4][8];
#pragma unroll
    for (int j = 0; j < 4; ++j) {
        mrow[j] = -1e30f;
        lrow[j] = 0.f;
#pragma unroll
        for (int u = 0; u < 8; ++u) oacc[j][u] = 0.f;
    }

    const int ktiles = blockIdx.x + 1;   // causal: only tiles with k <= q
    for (int kt = 0; kt < ktiles; ++kt) {
        const int k0 = kt * FBN;
        __syncthreads();   // prev PV done (and Q tile visible on first iter)

        // Load K (transposed into sKt) and V
#pragma unroll
        for (int it = 0; it < 8; ++it) {
            int e = tid * 4 + it * 1024;
            int r = e >> 7, c = e & 127;
            float4 kv = *(const float4*)(K + bOff + (size_t)(k0 + r) * DD + hOff + c);
            sKt[(c + 0) * SKT_LD + r] = kv.x;
            sKt[(c + 1) * SKT_LD + r] = kv.y;
            sKt[(c + 2) * SKT_LD + r] = kv.z;
            sKt[(c + 3) * SKT_LD + r] = kv.w;
            float4 vv = *(const float4*)(V + bOff + (size_t)(k0 + r) * DD + hOff + c);
            *(float4*)&sV[r * SV_LD + c] = vv;
        }
        __syncthreads();

        // S = (Q*scale) K^T   (4x4 per thread)
        float acc[4][4];
#pragma unroll
        for (int j = 0; j < 4; ++j)
#pragma unroll
            for (int i = 0; i < 4; ++i) acc[j][i] = 0.f;

        for (int k = 0; k < 128; k += 4) {
            float qf[4][4], kf[4][4];
#pragma unroll
            for (int j = 0; j < 4; ++j)
                *reinterpret_cast<float4*>(qf[j]) =
                    *reinterpret_cast<const float4*>(&sQ[(4 * ty + j) * SQ_LD + k]);
#pragma unroll
            for (int kk = 0; kk < 4; ++kk)
                *reinterpret_cast<float4*>(kf[kk]) =
                    *reinterpret_cast<const float4*>(&sKt[(k + kk) * SKT_LD + 4 * tx]);
#pragma unroll
            for (int j = 0; j < 4; ++j)
#pragma unroll
                for (int i = 0; i < 4; ++i) {
#pragma unroll
                    for (int kk = 0; kk < 4; ++kk)
                        acc[j][i] += qf[j][kk] * kf[kk][i];
                }
        }

        // Causal mask on diagonal tile
        if (kt == ktiles - 1) {
#pragma unroll
            for (int j = 0; j < 4; ++j)
#pragma unroll
                for (int i = 0; i < 4; ++i)
                    if (k0 + 4 * tx + i > q0 + 4 * ty + j) acc[j][i] = -1e30f;
        }

        // Online softmax update (row reductions across the 16 tx lanes)
#pragma unroll
        for (int j = 0; j < 4; ++j) {
            float mt = acc[j][0];
#pragma unroll
            for (int i = 1; i < 4; ++i) mt = fmaxf(mt, acc[j][i]);
            mt = fmaxf(mt, __shfl_xor_sync(0xffffffffu, mt, 1));
            mt = fmaxf(mt, __shfl_xor_sync(0xffffffffu, mt, 2));
            mt = fmaxf(mt, __shfl_xor_sync(0xffffffffu, mt, 4));
            mt = fmaxf(mt, __shfl_xor_sync(0xffffffffu, mt, 8));
            float mn = fmaxf(mrow[j], mt);
            float alpha = __expf(mrow[j] - mn);
            float rs = 0.f;
#pragma unroll
            for (int i = 0; i < 4; ++i) {
                float pv = __expf(acc[j][i] - mn);
                sP[(4 * ty + j) * SP_LD + 4 * tx + i] = pv;
                rs += pv;
            }
            rs += __shfl_xor_sync(0xffffffffu, rs, 1);
            rs += __shfl_xor_sync(0xffffffffu, rs, 2);
            rs += __shfl_xor_sync(0xffffffffu, rs, 4);
            rs += __shfl_xor_sync(0xffffffffu, rs, 8);
            lrow[j] = lrow[j] * alpha + rs;
            mrow[j] = mn;
#pragma unroll
            for (int u = 0; u < 8; ++u) oacc[j][u] *= alpha;
        }
        __syncthreads();

        // O += P @ V
        for (int c = 0; c < FBN; ++c) {
            float vf[8];
            *reinterpret_cast<float4*>(&vf[0]) =
                *reinterpret_cast<const float4*>(&sV[c * SV_LD + 8 * tx]);
            *reinterpret_cast<float4*>(&vf[4]) =
                *reinterpret_cast<const float4*>(&sV[c * SV_LD + 8 * tx + 4]);
#pragma unroll
            for (int j = 0; j < 4; ++j) {
                float pv = sP[(4 * ty + j) * SP_LD + c];
#pragma unroll
                for (int u = 0; u < 8; ++u) oacc[j][u] += pv * vf[u];
            }
        }
    }

    // Epilogue: normalize and write [B,L,H,HD]
#pragma unroll
    for (int j = 0; j < 4; ++j) {
        float inv = 1.0f / lrow[j];
        float* orow = O + bOff + (size_t)(q0 + 4 * ty + j) * DD + hOff + 8 * tx;
        float4 o0 = make_float4(oacc[j][0] * inv, oacc[j][1] * inv,
                                oacc[j][2] * inv, oacc[j][3] * inv);
        float4 o1 = make_float4(oacc[j][4] * inv, oacc[j][5] * inv,
                                oacc[j][6] * inv, oacc[j][7] * inv);
        *(float4*)(orow) = o0;
        *(float4*)(orow + 4) = o1;
    }
}

// ---------------------------------------------------------------------------
// Launch
// ---------------------------------------------------------------------------
extern "C" void kernel_launch(void* const* d_in, const int* in_sizes, int n_in,
                              void* d_out, int out_size) {
    const float* x  = (const float*)d_in[0];
    const float* Wq = (const float*)d_in[1];
    const float* Wk = (const float*)d_in[2];
    const float* Wv = (const float*)d_in[3];
    const float* Wo = (const float*)d_in[4];
    float* out = (float*)d_out;

    float *q, *k, *v, *attn;
    cudaGetSymbolAddress((void**)&q, g_q);
    cudaGetSymbolAddress((void**)&k, g_k);
    cudaGetSymbolAddress((void**)&v, g_v);
    cudaGetSymbolAddress((void**)&attn, g_attn);

    // 1. RoPE tables
    rope_tables_kernel<<<LL, 64>>>();

    // 2. QKV projections
    dim3 gemmGrid(DD / GBN, MM / GBM);   // (16, 64)
    gemm_ffma<<<gemmGrid, 256>>>(x, Wq, q, MM, DD, DD);
    gemm_ffma<<<gemmGrid, 256>>>(x, Wk, k, MM, DD, DD);
    gemm_ffma<<<gemmGrid, 256>>>(x, Wv, v, MM, DD, DD);

    // 3. RoPE on Q and K
    {
        size_t n2 = 2ull * BB * LL * HH * 64;   // 16,777,216
        rope_apply_kernel<<<(unsigned)(n2 / 256), 256>>>(q, k);
    }

    // 4. Flash attention (causal)
    cudaFuncSetAttribute(flash_attn_kernel,
                         cudaFuncAttributeMaxDynamicSharedMemorySize,
                         FLASH_SMEM_BYTES);
    dim3 faGrid(LL / FBM, BB * HH);   // (32, 64)
    flash_attn_kernel<<<faGrid, 256, FLASH_SMEM_BYTES>>>(q, k, v, attn);

    // 5. Output projection
    gemm_ffma<<<gemmGrid, 256>>>(attn, Wo, out, MM, DD, DD);
}

// round 4
// speedup vs baseline: 1.7832x; 1.7832x over previous
#include <cuda_runtime.h>
#include <cuda_bf16.h>
#include <math.h>
#include <stdint.h>

// Problem constants
#define BB   4
#define LL   2048
#define DD   2048
#define HH   16
#define HD   128
#define MM   (BB * LL)       // 8192
#define K3   6144            // 3 * DD (split-K stacking)

// ---------------------------------------------------------------------------
// Scratch (device globals; no allocation allowed)
// ---------------------------------------------------------------------------
__device__ float g_q[(size_t)MM * DD];
__device__ float g_k[(size_t)MM * DD];
__device__ float g_v[(size_t)MM * DD];
__device__ float g_attn[(size_t)MM * DD];
__device__ float g_cos[LL * (HD / 2)];
__device__ float g_sin[LL * (HD / 2)];
__device__ __align__(16) __nv_bfloat16 g_a3[(size_t)MM * K3];   // [M, 3K] = [Ah|Al|Ah]
__device__ __align__(16) __nv_bfloat16 g_b3[(size_t)DD * K3];   // [N, 3K] = [Wh|Wh|Wl]

// ---------------------------------------------------------------------------
// Helpers
// ---------------------------------------------------------------------------
__device__ __forceinline__ uint32_t smem_u32(const void* p) {
    uint32_t a;
    asm("{ .reg .u64 t; cvta.to.shared.u64 t, %1; cvt.u32.u64 %0, t; }" : "=r"(a) : "l"(p));
    return a;
}
__device__ __host__ __forceinline__ uint32_t sw128(uint32_t off) {
    return off ^ ((off >> 3) & 0x70);
}
#define CP_ASYNC16(dst, src) \
    asm volatile("cp.async.cg.shared.global [%0], [%1], 16;" :: "r"(dst), "l"(src))
#define CP_COMMIT() asm volatile("cp.async.commit_group;" ::: "memory")
#define CP_WAIT1()  asm volatile("cp.async.wait_group 1;" ::: "memory")
#define CP_WAIT0()  asm volatile("cp.async.wait_group 0;" ::: "memory")

#define LDSM_X4(r0, r1, r2, r3, addr) \
    asm volatile("ldmatrix.sync.aligned.m8n8.x4.shared.b16 {%0,%1,%2,%3}, [%4];" \
        : "=r"(r0), "=r"(r1), "=r"(r2), "=r"(r3) : "r"(addr))
#define LDSM_X2(r0, r1, addr) \
    asm volatile("ldmatrix.sync.aligned.m8n8.x2.shared.b16 {%0,%1}, [%2];" \
        : "=r"(r0), "=r"(r1) : "r"(addr))

#define MMA16816(d, a, b) \
    asm volatile("mma.sync.aligned.m16n8k16.row.col.f32.bf16.bf16.f32 " \
        "{%0,%1,%2,%3}, {%4,%5,%6,%7}, {%8,%9}, {%0,%1,%2,%3};" \
        : "+f"((d)[0]), "+f"((d)[1]), "+f"((d)[2]), "+f"((d)[3]) \
        : "r"((a)[0]), "r"((a)[1]), "r"((a)[2]), "r"((a)[3]), \
          "r"((b)[0]), "r"((b)[1]))

// ---------------------------------------------------------------------------
// RoPE tables
// ---------------------------------------------------------------------------
__global__ void rope_tables_kernel() {
    int t = blockIdx.x;
    int i = threadIdx.x;
    double inv = exp(-log(10000.0) * ((double)i / 64.0));
    float freq = (float)t * (float)inv;
    double ph = (double)freq;
    g_cos[t * 64 + i] = (float)cos(ph);
    g_sin[t * 64 + i] = (float)sin(ph);
}

// ---------------------------------------------------------------------------
// Split fp32 activations -> A3 bf16 [M, 6144] = [hi | lo | hi]
// ---------------------------------------------------------------------------
__global__ void split_x_kernel(const float* __restrict__ X, __nv_bfloat16* __restrict__ A3) {
    size_t idx = (size_t)blockIdx.x * blockDim.x + threadIdx.x;   // over M*1024
    size_t m = idx >> 10;
    int kp = (int)(idx & 1023);
    float2 xv = *(const float2*)(X + (m << 11) + 2 * kp);
    __nv_bfloat16 h0 = __float2bfloat16(xv.x);
    __nv_bfloat16 h1 = __float2bfloat16(xv.y);
    __nv_bfloat16 l0 = __float2bfloat16(xv.x - __bfloat162float(h0));
    __nv_bfloat16 l1 = __float2bfloat16(xv.y - __bfloat162float(h1));
    __nv_bfloat162 h2; h2.x = h0; h2.y = h1;
    __nv_bfloat162 l2; l2.x = l0; l2.y = l1;
    __nv_bfloat162* out = (__nv_bfloat162*)(A3 + m * K3);
    out[kp] = h2;
    out[1024 + kp] = l2;
    out[2048 + kp] = h2;
}

// ---------------------------------------------------------------------------
// Split + transpose weight W[K,N] -> B3 bf16 [N, 6144] = [Wh | Wh | Wl]
// ---------------------------------------------------------------------------
__global__ void split_w_kernel(const float* __restrict__ W, __nv_bfloat16* __restrict__ B3) {
    __shared__ float t[32][33];
    int n0 = blockIdx.x * 32, k0 = blockIdx.y * 32;
    int tx = threadIdx.x, ty = threadIdx.y;   // 32 x 8
#pragma unroll
    for (int i = 0; i < 4; ++i)
        t[ty + 8 * i][tx] = W[(size_t)(k0 + ty + 8 * i) * DD + n0 + tx];
    __syncthreads();
#pragma unroll
    for (int i = 0; i < 4; ++i) {
        int n = n0 + ty + 8 * i;
        int k = k0 + tx;
        float v = t[tx][ty + 8 * i];
        __nv_bfloat16 h = __float2bfloat16(v);
        __nv_bfloat16 l = __float2bfloat16(v - __bfloat162float(h));
        __nv_bfloat16* row = B3 + (size_t)n * K3;
        row[k] = h;
        row[2048 + k] = h;
        row[4096 + k] = l;
    }
}

// ---------------------------------------------------------------------------
// HMMA (mma.sync) bf16 GEMM: C[M, 2048] = A3[M, 6144] (.) B3[2048, 6144]^T
// CTA tile 128x128, BK=64, 8 warps (2x4), cp.async double buffer, SW128 smem.
// ---------------------------------------------------------------------------
#define HBK 64
#define HNKB (K3 / HBK)                 // 96
#define HTILE_BYTES (128 * 128)         // 16KB per tile (128 rows x 128B)
#define HSMEM (4 * HTILE_BYTES)         // 64KB total

__device__ __forceinline__ void hmma_stage_load(
    const __nv_bfloat16* aBase, const __nv_bfloat16* bBase,
    uint32_t sAu, uint32_t sBu, int kb, int tid)
{
#pragma unroll
    for (int t = 0; t < 4; ++t) {
        int c = tid + 256 * t;            // 0..1023
        int row = c >> 3;                 // 0..127
        int cc = c & 7;                   // 16B chunk in row
        uint32_t dst = sw128((uint32_t)(row * 128 + cc * 16));
        const void* sa = (const void*)(aBase + (size_t)row * K3 + kb * HBK + cc * 8);
        const void* sb = (const void*)(bBase + (size_t)row * K3 + kb * HBK + cc * 8);
        CP_ASYNC16(sAu + dst, sa);
        CP_ASYNC16(sBu + dst, sb);
    }
}

__global__ __launch_bounds__(256) void gemm_hmma(
    const __nv_bfloat16* __restrict__ A,   // [M, K3]
    const __nv_bfloat16* __restrict__ Bm,  // [N=2048, K3]
    float* __restrict__ C)
{
    extern __shared__ char smem[];
    const int tid = threadIdx.x;
    const int wid = tid >> 5;
    const int lane = tid & 31;
    const int m0 = blockIdx.y * 128;
    const int n0 = blockIdx.x * 128;
    const int warpM = (wid >> 2) * 64;    // 0 or 64
    const int warpN = (wid & 3) * 32;     // 0..96

    uint32_t sAu[2] = { smem_u32(smem), smem_u32(smem + HTILE_BYTES) };
    uint32_t sBu[2] = { smem_u32(smem + 2 * HTILE_BYTES), smem_u32(smem + 3 * HTILE_BYTES) };

    const __nv_bfloat16* aBase = A + (size_t)m0 * K3;
    const __nv_bfloat16* bBase = Bm + (size_t)n0 * K3;

    float acc[4][4][4];
#pragma unroll
    for (int mi = 0; mi < 4; ++mi)
#pragma unroll
        for (int ni = 0; ni < 4; ++ni)
#pragma unroll
            for (int u = 0; u < 4; ++u) acc[mi][ni][u] = 0.f;

    // lane-dependent ldmatrix row/col (element units)
    const int rowA = warpM + ((lane >> 3) & 1) * 8 + (lane & 7);
    const int colA = (lane >> 4) * 8;
    const int rowB = warpN + (lane & 7);
    const int colB = ((lane >> 3) & 1) * 8;

    // prologue
    hmma_stage_load(aBase, bBase, sAu[0], sBu[0], 0, tid);
    CP_COMMIT();

    for (int kb = 0; kb < HNKB; ++kb) {
        const int buf = kb & 1;
        if (kb + 1 < HNKB) {
            hmma_stage_load(aBase, bBase, sAu[buf ^ 1], sBu[buf ^ 1], kb + 1, tid);
            CP_COMMIT();
            CP_WAIT1();
        } else {
            CP_WAIT0();
        }
        __syncthreads();

#pragma unroll
        for (int ks = 0; ks < 4; ++ks) {
            uint32_t af[4][4];
#pragma unroll
            for (int mi = 0; mi < 4; ++mi) {
                uint32_t addr = sAu[buf] +
                    sw128((uint32_t)((rowA + mi * 16) * 128 + (ks * 16 + colA) * 2));
                LDSM_X4(af[mi][0], af[mi][1], af[mi][2], af[mi][3], addr);
            }
            uint32_t bf[4][2];
#pragma unroll
            for (int ni = 0; ni < 4; ++ni) {
                uint32_t addr = sBu[buf] +
                    sw128((uint32_t)((rowB + ni * 8) * 128 + (ks * 16 + colB) * 2));
                LDSM_X2(bf[ni][0], bf[ni][1], addr);
            }
#pragma unroll
            for (int mi = 0; mi < 4; ++mi)
#pragma unroll
                for (int ni = 0; ni < 4; ++ni)
                    MMA16816(acc[mi][ni], af[mi], bf[ni]);
        }
        __syncthreads();
    }

    // epilogue
    const int gRow = lane >> 2;       // 0..7
    const int gCol = (lane & 3) * 2;  // 0..6
#pragma unroll
    for (int mi = 0; mi < 4; ++mi) {
#pragma unroll
        for (int ni = 0; ni < 4; ++ni) {
            int r = m0 + warpM + mi * 16 + gRow;
            int cix = n0 + warpN + ni * 8 + gCol;
            float2 v0 = make_float2(acc[mi][ni][0], acc[mi][ni][1]);
            float2 v1 = make_float2(acc[mi][ni][2], acc[mi][ni][3]);
            *(float2*)(C + (size_t)r * DD + cix) = v0;
            *(float2*)(C + (size_t)(r + 8) * DD + cix) = v1;
        }
    }
}

// ---------------------------------------------------------------------------
// RoPE apply, in-place on q and k (layout [B,L,H,HD])
// ---------------------------------------------------------------------------
__global__ void rope_apply_kernel(float* __restrict__ q, float* __restrict__ k) {
    const size_t n = (size_t)BB * LL * HH * 64;
    size_t idx = (size_t)blockIdx.x * blockDim.x + threadIdx.x;
    float* p = q;
    size_t e = idx;
    if (e >= n) { p = k; e -= n; }
    int i = (int)(e & 63);
    size_t rest = e >> 6;
    int h = (int)(rest & 15);
    size_t bl = rest >> 4;
    int l = (int)(bl & (LL - 1));
    size_t base = bl * DD + (size_t)h * HD;
    float c = g_cos[l * 64 + i];
    float s = g_sin[l * 64 + i];
    float x1 = p[base + i];
    float x2 = p[base + i + 64];
    p[base + i]      = x1 * c - x2 * s;
    p[base + i + 64] = x2 * c + x1 * s;
}

// ---------------------------------------------------------------------------
// Flash attention, causal
// ---------------------------------------------------------------------------
#define FBM 64
#define FBN 64
#define SQ_LD 132
#define SKT_LD 68
#define SV_LD 132
#define SP_LD 68
#define FLASH_SMEM_FLOATS (FBM*SQ_LD + HD*SKT_LD + FBN*SV_LD + FBM*SP_LD)
#define FLASH_SMEM_BYTES (FLASH_SMEM_FLOATS * 4)

__global__ __launch_bounds__(256, 1) void flash_attn_kernel(
    const float* __restrict__ Q, const float* __restrict__ K,
    const float* __restrict__ V, float* __restrict__ O)
{
    extern __shared__ float sm[];
    float* sQ  = sm;
    float* sKt = sQ + FBM * SQ_LD;
    float* sV  = sKt + HD * SKT_LD;
    float* sP  = sV + FBN * SV_LD;

    const int tid = threadIdx.x;
    const int tx = tid & 15;
    const int ty = tid >> 4;
    const int b = blockIdx.y >> 4;
    const int h = blockIdx.y & 15;
    const int q0 = blockIdx.x * FBM;
    const float scale = 0.08838834764831845f;

    const size_t bOff = (size_t)b * LL * DD;
    const size_t hOff = (size_t)h * HD;

#pragma unroll
    for (int it = 0; it < 8; ++it) {
        int e = tid * 4 + it * 1024;
        int r = e >> 7, c = e & 127;
        float4 v = *(const float4*)(Q + bOff + (size_t)(q0 + r) * DD + hOff + c);
        v.x *= scale; v.y *= scale; v.z *= scale; v.w *= scale;
        *(float4*)&sQ[r * SQ_LD + c] = v;
    }

    float mrow[4], lrow[4], oacc[4][8];
#pragma unroll
    for (int j = 0; j < 4; ++j) {
        mrow[j] = -1e30f;
        lrow[j] = 0.f;
#pragma unroll
        for (int u = 0; u < 8; ++u) oacc[j][u] = 0.f;
    }

    const int ktiles = blockIdx.x + 1;
    for (int kt = 0; kt < ktiles; ++kt) {
        const int k0 = kt * FBN;
        __syncthreads();

#pragma unroll
        for (int it = 0; it < 8; ++it) {
            int e = tid * 4 + it * 1024;
            int r = e >> 7, c = e & 127;
            float4 kv = *(const float4*)(K + bOff + (size_t)(k0 + r) * DD + hOff + c);
            sKt[(c + 0) * SKT_LD + r] = kv.x;
            sKt[(c + 1) * SKT_LD + r] = kv.y;
            sKt[(c + 2) * SKT_LD + r] = kv.z;
            sKt[(c + 3) * SKT_LD + r] = kv.w;
            float4 vv = *(const float4*)(V + bOff + (size_t)(k0 + r) * DD + hOff + c);
            *(float4*)&sV[r * SV_LD + c] = vv;
        }
        __syncthreads();

        float acc[4][4];
#pragma unroll
        for (int j = 0; j < 4; ++j)
#pragma unroll
            for (int i = 0; i < 4; ++i) acc[j][i] = 0.f;

        for (int k = 0; k < 128; k += 4) {
            float qf[4][4], kf[4][4];
#pragma unroll
            for (int j = 0; j < 4; ++j)
                *reinterpret_cast<float4*>(qf[j]) =
                    *reinterpret_cast<const float4*>(&sQ[(4 * ty + j) * SQ_LD + k]);
#pragma unroll
            for (int kk = 0; kk < 4; ++kk)
                *reinterpret_cast<float4*>(kf[kk]) =
                    *reinterpret_cast<const float4*>(&sKt[(k + kk) * SKT_LD + 4 * tx]);
#pragma unroll
            for (int j = 0; j < 4; ++j)
#pragma unroll
                for (int i = 0; i < 4; ++i) {
#pragma unroll
                    for (int kk = 0; kk < 4; ++kk)
                        acc[j][i] += qf[j][kk] * kf[kk][i];
                }
        }

        if (kt == ktiles - 1) {
#pragma unroll
            for (int j = 0; j < 4; ++j)
#pragma unroll
                for (int i = 0; i < 4; ++i)
                    if (k0 + 4 * tx + i > q0 + 4 * ty + j) acc[j][i] = -1e30f;
        }

#pragma unroll
        for (int j = 0; j < 4; ++j) {
            float mt = acc[j][0];
#pragma unroll
            for (int i = 1; i < 4; ++i) mt = fmaxf(mt, acc[j][i]);
            mt = fmaxf(mt, __shfl_xor_sync(0xffffffffu, mt, 1));
            mt = fmaxf(mt, __shfl_xor_sync(0xffffffffu, mt, 2));
            mt = fmaxf(mt, __shfl_xor_sync(0xffffffffu, mt, 4));
            mt = fmaxf(mt, __shfl_xor_sync(0xffffffffu, mt, 8));
            float mn = fmaxf(mrow[j], mt);
            float alpha = __expf(mrow[j] - mn);
            float rs = 0.f;
#pragma unroll
            for (int i = 0; i < 4; ++i) {
                float pv = __expf(acc[j][i] - mn);
                sP[(4 * ty + j) * SP_LD + 4 * tx + i] = pv;
                rs += pv;
            }
            rs += __shfl_xor_sync(0xffffffffu, rs, 1);
            rs += __shfl_xor_sync(0xffffffffu, rs, 2);
            rs += __shfl_xor_sync(0xffffffffu, rs, 4);
            rs += __shfl_xor_sync(0xffffffffu, rs, 8);
            lrow[j] = lrow[j] * alpha + rs;
            mrow[j] = mn;
#pragma unroll
            for (int u = 0; u < 8; ++u) oacc[j][u] *= alpha;
        }
        __syncthreads();

        for (int c = 0; c < FBN; ++c) {
            float vf[8];
            *reinterpret_cast<float4*>(&vf[0]) =
                *reinterpret_cast<const float4*>(&sV[c * SV_LD + 8 * tx]);
            *reinterpret_cast<float4*>(&vf[4]) =
                *reinterpret_cast<const float4*>(&sV[c * SV_LD + 8 * tx + 4]);
#pragma unroll
            for (int j = 0; j < 4; ++j) {
                float pv = sP[(4 * ty + j) * SP_LD + c];
#pragma unroll
                for (int u = 0; u < 8; ++u) oacc[j][u] += pv * vf[u];
            }
        }
    }

#pragma unroll
    for (int j = 0; j < 4; ++j) {
        float inv = 1.0f / lrow[j];
        float* orow = O + bOff + (size_t)(q0 + 4 * ty + j) * DD + hOff + 8 * tx;
        float4 o0 = make_float4(oacc[j][0] * inv, oacc[j][1] * inv,
                                oacc[j][2] * inv, oacc[j][3] * inv);
        float4 o1 = make_float4(oacc[j][4] * inv, oacc[j][5] * inv,
                                oacc[j][6] * inv, oacc[j][7] * inv);
        *(float4*)(orow) = o0;
        *(float4*)(orow + 4) = o1;
    }
}

// ---------------------------------------------------------------------------
// Launch
// ---------------------------------------------------------------------------
extern "C" void kernel_launch(void* const* d_in, const int* in_sizes, int n_in,
                              void* d_out, int out_size) {
    const float* x  = (const float*)d_in[0];
    const float* Wq = (const float*)d_in[1];
    const float* Wk = (const float*)d_in[2];
    const float* Wv = (const float*)d_in[3];
    const float* Wo = (const float*)d_in[4];
    float* out = (float*)d_out;

    float *q, *k, *v, *attn;
    __nv_bfloat16 *a3, *b3;
    cudaGetSymbolAddress((void**)&q, g_q);
    cudaGetSymbolAddress((void**)&k, g_k);
    cudaGetSymbolAddress((void**)&v, g_v);
    cudaGetSymbolAddress((void**)&attn, g_attn);
    cudaGetSymbolAddress((void**)&a3, g_a3);
    cudaGetSymbolAddress((void**)&b3, g_b3);

    cudaFuncSetAttribute(gemm_hmma, cudaFuncAttributeMaxDynamicSharedMemorySize, HSMEM);
    cudaFuncSetAttribute(flash_attn_kernel,
                         cudaFuncAttributeMaxDynamicSharedMemorySize, FLASH_SMEM_BYTES);

    // 1. RoPE tables
    rope_tables_kernel<<<LL, 64>>>();

    // 2. Split x once (shared by Q/K/V projections)
    split_x_kernel<<<(unsigned)(((size_t)MM * 1024) / 256), 256>>>(x, a3);

    dim3 wGrid(64, 64);
    dim3 wBlk(32, 8);
    dim3 gGrid(DD / 128, MM / 128);   // (16, 64)

    // 3. QKV projections on tensor cores (HMMA)
    split_w_kernel<<<wGrid, wBlk>>>(Wq, b3);
    gemm_hmma<<<gGrid, 256, HSMEM>>>(a3, b3, q);
    split_w_kernel<<<wGrid, wBlk>>>(Wk, b3);
    gemm_hmma<<<gGrid, 256, HSMEM>>>(a3, b3, k);
    split_w_kernel<<<wGrid, wBlk>>>(Wv, b3);
    gemm_hmma<<<gGrid, 256, HSMEM>>>(a3, b3, v);

    // 4. RoPE on Q and K
    {
        size_t n2 = 2ull * BB * LL * HH * 64;
        rope_apply_kernel<<<(unsigned)(n2 / 256), 256>>>(q, k);
    }

    // 5. Flash attention (causal)
    dim3 faGrid(LL / FBM, BB * HH);
    flash_attn_kernel<<<faGrid, 256, FLASH_SMEM_BYTES>>>(q, k, v, attn);

    // 6. Output projection
    split_x_kernel<<<(unsigned)(((size_t)MM * 1024) / 256), 256>>>(attn, a3);
    split_w_kernel<<<wGrid, wBlk>>>(Wo, b3);
    gemm_hmma<<<gGrid, 256, HSMEM>>>(a3, b3, out);
}

// round 6
// speedup vs baseline: 3.2023x; 1.7958x over previous
#include <cuda_runtime.h>
#include <cuda_bf16.h>
#include <math.h>
#include <stdint.h>

// Problem constants
#define BB   4
#define LL   2048
#define DD   2048
#define HH   16
#define HD   128
#define MM   (BB * LL)       // 8192
#define K3   6144            // 3 * DD (split-K stacking)

// ---------------------------------------------------------------------------
// Scratch (device globals; no allocation allowed)
// ---------------------------------------------------------------------------
__device__ float g_q[(size_t)MM * DD];
__device__ float g_k[(size_t)MM * DD];
__device__ float g_v[(size_t)MM * DD];
__device__ float g_attn[(size_t)MM * DD];
__device__ float g_cos[LL * (HD / 2)];
__device__ float g_sin[LL * (HD / 2)];
__device__ __align__(16) __nv_bfloat16 g_a3[(size_t)MM * K3];   // [M, 3K] = [Ah|Al|Ah]
__device__ __align__(16) __nv_bfloat16 g_b3[(size_t)DD * K3];   // [N, 3K] = [Wh|Wh|Wl]

// ---------------------------------------------------------------------------
// Helpers
// ---------------------------------------------------------------------------
__device__ __forceinline__ uint32_t smem_u32(const void* p) {
    uint32_t a;
    asm("{ .reg .u64 t; cvta.to.shared.u64 t, %1; cvt.u32.u64 %0, t; }" : "=r"(a) : "l"(p));
    return a;
}
__device__ __host__ __forceinline__ uint32_t sw128(uint32_t off) {
    return off ^ ((off >> 3) & 0x70);
}
#define CP_ASYNC16(dst, src) \
    asm volatile("cp.async.cg.shared.global [%0], [%1], 16;" :: "r"(dst), "l"(src))
#define CP_COMMIT() asm volatile("cp.async.commit_group;" ::: "memory")
#define CP_WAIT1()  asm volatile("cp.async.wait_group 1;" ::: "memory")
#define CP_WAIT0()  asm volatile("cp.async.wait_group 0;" ::: "memory")

#define LDSM_X4(r0, r1, r2, r3, addr) \
    asm volatile("ldmatrix.sync.aligned.m8n8.x4.shared.b16 {%0,%1,%2,%3}, [%4];" \
        : "=r"(r0), "=r"(r1), "=r"(r2), "=r"(r3) : "r"(addr))
#define LDSM_X4_T(r0, r1, r2, r3, addr) \
    asm volatile("ldmatrix.sync.aligned.m8n8.x4.trans.shared.b16 {%0,%1,%2,%3}, [%4];" \
        : "=r"(r0), "=r"(r1), "=r"(r2), "=r"(r3) : "r"(addr))
#define LDSM_X2(r0, r1, addr) \
    asm volatile("ldmatrix.sync.aligned.m8n8.x2.shared.b16 {%0,%1}, [%2];" \
        : "=r"(r0), "=r"(r1) : "r"(addr))

#define MMA16816(d, a0, a1, a2, a3, b0, b1) \
    asm volatile("mma.sync.aligned.m16n8k16.row.col.f32.bf16.bf16.f32 " \
        "{%0,%1,%2,%3}, {%4,%5,%6,%7}, {%8,%9}, {%0,%1,%2,%3};" \
        : "+f"((d)[0]), "+f"((d)[1]), "+f"((d)[2]), "+f"((d)[3]) \
        : "r"(a0), "r"(a1), "r"(a2), "r"(a3), "r"(b0), "r"(b1))

__device__ __forceinline__ uint32_t pack_bf16(float a, float b) {
    __nv_bfloat162 t = __floats2bfloat162_rn(a, b);
    return *(uint32_t*)&t;
}

// ---------------------------------------------------------------------------
// RoPE tables
// ---------------------------------------------------------------------------
__global__ void rope_tables_kernel() {
    int t = blockIdx.x;
    int i = threadIdx.x;
    double inv = exp(-log(10000.0) * ((double)i / 64.0));
    float freq = (float)t * (float)inv;
    double ph = (double)freq;
    g_cos[t * 64 + i] = (float)cos(ph);
    g_sin[t * 64 + i] = (float)sin(ph);
}

// ---------------------------------------------------------------------------
// Split fp32 activations -> A3 bf16 [M, 6144] = [hi | lo | hi]
// ---------------------------------------------------------------------------
__global__ void split_x_kernel(const float* __restrict__ X, __nv_bfloat16* __restrict__ A3) {
    size_t idx = (size_t)blockIdx.x * blockDim.x + threadIdx.x;   // over M*1024
    size_t m = idx >> 10;
    int kp = (int)(idx & 1023);
    float2 xv = *(const float2*)(X + (m << 11) + 2 * kp);
    __nv_bfloat16 h0 = __float2bfloat16(xv.x);
    __nv_bfloat16 h1 = __float2bfloat16(xv.y);
    __nv_bfloat16 l0 = __float2bfloat16(xv.x - __bfloat162float(h0));
    __nv_bfloat16 l1 = __float2bfloat16(xv.y - __bfloat162float(h1));
    __nv_bfloat162 h2; h2.x = h0; h2.y = h1;
    __nv_bfloat162 l2; l2.x = l0; l2.y = l1;
    __nv_bfloat162* out = (__nv_bfloat162*)(A3 + m * K3);
    out[kp] = h2;
    out[1024 + kp] = l2;
    out[2048 + kp] = h2;
}

// ---------------------------------------------------------------------------
// Split + transpose weight W[K,N] -> B3 bf16 [N, 6144] = [Wh | Wh | Wl]
// ---------------------------------------------------------------------------
__global__ void split_w_kernel(const float* __restrict__ W, __nv_bfloat16* __restrict__ B3) {
    __shared__ float t[32][33];
    int n0 = blockIdx.x * 32, k0 = blockIdx.y * 32;
    int tx = threadIdx.x, ty = threadIdx.y;   // 32 x 8
#pragma unroll
    for (int i = 0; i < 4; ++i)
        t[ty + 8 * i][tx] = W[(size_t)(k0 + ty + 8 * i) * DD + n0 + tx];
    __syncthreads();
#pragma unroll
    for (int i = 0; i < 4; ++i) {
        int n = n0 + ty + 8 * i;
        int k = k0 + tx;
        float v = t[tx][ty + 8 * i];
        __nv_bfloat16 h = __float2bfloat16(v);
        __nv_bfloat16 l = __float2bfloat16(v - __bfloat162float(h));
        __nv_bfloat16* row = B3 + (size_t)n * K3;
        row[k] = h;
        row[2048 + k] = h;
        row[4096 + k] = l;
    }
}

// ---------------------------------------------------------------------------
// HMMA bf16 GEMM: C[M, 2048] = A3[M, 6144] (.) B3[2048, 6144]^T
// ---------------------------------------------------------------------------
#define HBK 64
#define HNKB (K3 / HBK)                 // 96
#define HTILE_BYTES (128 * 128)         // 16KB per tile
#define HSMEM (4 * HTILE_BYTES)         // 64KB total

__device__ __forceinline__ void hmma_stage_load(
    const __nv_bfloat16* aBase, const __nv_bfloat16* bBase,
    uint32_t sAu, uint32_t sBu, int kb, int tid)
{
#pragma unroll
    for (int t = 0; t < 4; ++t) {
        int c = tid + 256 * t;
        int row = c >> 3;
        int cc = c & 7;
        uint32_t dst = sw128((uint32_t)(row * 128 + cc * 16));
        const void* sa = (const void*)(aBase + (size_t)row * K3 + kb * HBK + cc * 8);
        const void* sb = (const void*)(bBase + (size_t)row * K3 + kb * HBK + cc * 8);
        CP_ASYNC16(sAu + dst, sa);
        CP_ASYNC16(sBu + dst, sb);
    }
}

__global__ __launch_bounds__(256, 2) void gemm_hmma(
    const __nv_bfloat16* __restrict__ A,
    const __nv_bfloat16* __restrict__ Bm,
    float* __restrict__ C)
{
    extern __shared__ char smem[];
    const int tid = threadIdx.x;
    const int wid = tid >> 5;
    const int lane = tid & 31;
    const int m0 = blockIdx.y * 128;
    const int n0 = blockIdx.x * 128;
    const int warpM = (wid >> 2) * 64;
    const int warpN = (wid & 3) * 32;

    uint32_t sAu[2] = { smem_u32(smem), smem_u32(smem + HTILE_BYTES) };
    uint32_t sBu[2] = { smem_u32(smem + 2 * HTILE_BYTES), smem_u32(smem + 3 * HTILE_BYTES) };

    const __nv_bfloat16* aBase = A + (size_t)m0 * K3;
    const __nv_bfloat16* bBase = Bm + (size_t)n0 * K3;

    float acc[4][4][4];
#pragma unroll
    for (int mi = 0; mi < 4; ++mi)
#pragma unroll
        for (int ni = 0; ni < 4; ++ni)
#pragma unroll
            for (int u = 0; u < 4; ++u) acc[mi][ni][u] = 0.f;

    const int rowA = warpM + ((lane >> 3) & 1) * 8 + (lane & 7);
    const int colA = (lane >> 4) * 8;
    const int rowB = warpN + (lane & 7);
    const int colB = ((lane >> 3) & 1) * 8;

    hmma_stage_load(aBase, bBase, sAu[0], sBu[0], 0, tid);
    CP_COMMIT();

    for (int kb = 0; kb < HNKB; ++kb) {
        const int buf = kb & 1;
        if (kb + 1 < HNKB) {
            hmma_stage_load(aBase, bBase, sAu[buf ^ 1], sBu[buf ^ 1], kb + 1, tid);
            CP_COMMIT();
            CP_WAIT1();
        } else {
            CP_WAIT0();
        }
        __syncthreads();

#pragma unroll
        for (int ks = 0; ks < 4; ++ks) {
            uint32_t af[4][4];
#pragma unroll
            for (int mi = 0; mi < 4; ++mi) {
                uint32_t addr = sAu[buf] +
                    sw128((uint32_t)((rowA + mi * 16) * 128 + (ks * 16 + colA) * 2));
                LDSM_X4(af[mi][0], af[mi][1], af[mi][2], af[mi][3], addr);
            }
            uint32_t bf[4][2];
#pragma unroll
            for (int ni = 0; ni < 4; ++ni) {
                uint32_t addr = sBu[buf] +
                    sw128((uint32_t)((rowB + ni * 8) * 128 + (ks * 16 + colB) * 2));
                LDSM_X2(bf[ni][0], bf[ni][1], addr);
            }
#pragma unroll
            for (int mi = 0; mi < 4; ++mi)
#pragma unroll
                for (int ni = 0; ni < 4; ++ni)
                    MMA16816(acc[mi][ni], af[mi][0], af[mi][1], af[mi][2], af[mi][3],
                             bf[ni][0], bf[ni][1]);
        }
        __syncthreads();
    }

    const int gRow = lane >> 2;
    const int gCol = (lane & 3) * 2;
#pragma unroll
    for (int mi = 0; mi < 4; ++mi) {
#pragma unroll
        for (int ni = 0; ni < 4; ++ni) {
            int r = m0 + warpM + mi * 16 + gRow;
            int cix = n0 + warpN + ni * 8 + gCol;
            *(float2*)(C + (size_t)r * DD + cix) = make_float2(acc[mi][ni][0], acc[mi][ni][1]);
            *(float2*)(C + (size_t)(r + 8) * DD + cix) = make_float2(acc[mi][ni][2], acc[mi][ni][3]);
        }
    }
}

// ---------------------------------------------------------------------------
// RoPE apply, in-place on q and k (layout [B,L,H,HD])
// ---------------------------------------------------------------------------
__global__ void rope_apply_kernel(float* __restrict__ q, float* __restrict__ k) {
    const size_t n = (size_t)BB * LL * HH * 64;
    size_t idx = (size_t)blockIdx.x * blockDim.x + threadIdx.x;
    float* p = q;
    size_t e = idx;
    if (e >= n) { p = k; e -= n; }
    int i = (int)(e & 63);
    size_t rest = e >> 6;
    int h = (int)(rest & 15);
    size_t bl = rest >> 4;
    int l = (int)(bl & (LL - 1));
    size_t base = bl * DD + (size_t)h * HD;
    float c = g_cos[l * 64 + i];
    float s = g_sin[l * 64 + i];
    float x1 = p[base + i];
    float x2 = p[base + i + 64];
    p[base + i]      = x1 * c - x2 * s;
    p[base + i + 64] = x2 * c + x1 * s;
}

// ---------------------------------------------------------------------------
// Flash attention (HMMA, split precision). CTA: 128 q-rows x 64 kv per iter.
// 8 warps, each owns 16 q rows. Q/K/V converted to bf16 hi/lo in smem.
// S = QhKh + QlKh + QhKl;  O += PhVh + PlVh + PhVl.
// smem panels: [panel][rows][128B] with sw128 swizzle.
//   Qh 0 (32K), Ql 32K, Kh 64K (16K), Kl 80K, Vh 96K, Vl 112K. Total 128K.
// ---------------------------------------------------------------------------
#define FL_SMEM (128 * 1024)

__global__ __launch_bounds__(256, 1) void flash_hmma(
    const float* __restrict__ Q, const float* __restrict__ K,
    const float* __restrict__ V, float* __restrict__ O)
{
    extern __shared__ char sm[];
    const uint32_t sQh = smem_u32(sm);
    const uint32_t sQl = sQh + 32768;
    const uint32_t sKh = sQh + 65536;
    const uint32_t sKl = sQh + 81920;
    const uint32_t sVh = sQh + 98304;
    const uint32_t sVl = sQh + 114688;

    const int tid = threadIdx.x;
    const int wid = tid >> 5;
    const int lane = tid & 31;
    const int b = blockIdx.y >> 4;
    const int h = blockIdx.y & 15;
    const int q0 = blockIdx.x * 128;
    const float scale = 0.08838834764831845f;   // 1/sqrt(128)

    const size_t bOff = (size_t)b * LL * DD;
    const size_t hOff = (size_t)h * HD;

    // ---- Load Q (scaled), split into hi/lo bf16 panels ----
#pragma unroll
    for (int i = 0; i < 16; ++i) {
        int idx = tid + 256 * i;           // over 128*32 float4
        int row = idx >> 5;
        int col = (idx & 31) * 4;
        float4 v = *(const float4*)(Q + bOff + (size_t)(q0 + row) * DD + hOff + col);
        v.x *= scale; v.y *= scale; v.z *= scale; v.w *= scale;
        float hx = __bfloat162float(__float2bfloat16(v.x));
        float hy = __bfloat162float(__float2bfloat16(v.y));
        float hz = __bfloat162float(__float2bfloat16(v.z));
        float hw = __bfloat162float(__float2bfloat16(v.w));
        uint2 hi2 = make_uint2(pack_bf16(hx, hy), pack_bf16(hz, hw));
        uint2 lo2 = make_uint2(pack_bf16(v.x - hx, v.y - hy), pack_bf16(v.z - hz, v.w - hw));
        uint32_t off = (uint32_t)(col >> 6) * 16384 + sw128((uint32_t)(row * 128 + (col & 63) * 2));
        *reinterpret_cast<uint2*>((char*)sm + off) = hi2;
        *reinterpret_cast<uint2*>((char*)sm + off + 32768) = lo2;
    }

    float oacc[16][4];
#pragma unroll
    for (int nt = 0; nt < 16; ++nt)
#pragma unroll
        for (int u = 0; u < 4; ++u) oacc[nt][u] = 0.f;
    float mrow[2] = { -1e30f, -1e30f };
    float lrow[2] = { 0.f, 0.f };

    const int iters = 2 * (blockIdx.x + 1);
    // ldsm address components
    const int arow = 16 * wid + ((lane >> 3) & 1) * 8 + (lane & 7);
    const int acol8 = (lane >> 4) * 8;           // k sub-col for A
    const int brow = (lane & 7) + ((lane >> 4) << 3);  // n row within 16-group
    const int bcol8 = ((lane >> 3) & 1) * 8;     // k sub-col for B
    const int vrow16 = lane & 15;                // k row within 16 for trans
    const int vcol8 = (lane >> 4) << 3;          // n sub-col for trans

    for (int kt = 0; kt < iters; ++kt) {
        const int k0g = kt * 64;
        __syncthreads();
        // ---- Load K,V tile (64x128 fp32), split to hi/lo bf16 ----
#pragma unroll
        for (int i = 0; i < 8; ++i) {
            int idx = tid + 256 * i;       // over 64*32 float4
            int row = idx >> 5;
            int col = (idx & 31) * 4;
            uint32_t off = (uint32_t)(col >> 6) * 8192 + sw128((uint32_t)(row * 128 + (col & 63) * 2));
            float4 kv = *(const float4*)(K + bOff + (size_t)(k0g + row) * DD + hOff + col);
            float hx = __bfloat162float(__float2bfloat16(kv.x));
            float hy = __bfloat162float(__float2bfloat16(kv.y));
            float hz = __bfloat162float(__float2bfloat16(kv.z));
            float hw = __bfloat162float(__float2bfloat16(kv.w));
            *reinterpret_cast<uint2*>((char*)sm + 65536 + off) =
                make_uint2(pack_bf16(hx, hy), pack_bf16(hz, hw));
            *reinterpret_cast<uint2*>((char*)sm + 81920 + off) =
                make_uint2(pack_bf16(kv.x - hx, kv.y - hy), pack_bf16(kv.z - hz, kv.w - hw));
            float4 vv = *(const float4*)(V + bOff + (size_t)(k0g + row) * DD + hOff + col);
            hx = __bfloat162float(__float2bfloat16(vv.x));
            hy = __bfloat162float(__float2bfloat16(vv.y));
            hz = __bfloat162float(__float2bfloat16(vv.z));
            hw = __bfloat162float(__float2bfloat16(vv.w));
            *reinterpret_cast<uint2*>((char*)sm + 98304 + off) =
                make_uint2(pack_bf16(hx, hy), pack_bf16(hz, hw));
            *reinterpret_cast<uint2*>((char*)sm + 114688 + off) =
                make_uint2(pack_bf16(vv.x - hx, vv.y - hy), pack_bf16(vv.z - hz, vv.w - hw));
        }
        __syncthreads();

        // ---- S = Q K^T (split, 3 products) ----
        float sacc[8][4];
#pragma unroll
        for (int nt = 0; nt < 8; ++nt)
#pragma unroll
            for (int u = 0; u < 4; ++u) sacc[nt][u] = 0.f;

#pragma unroll
        for (int ks = 0; ks < 8; ++ks) {
            const uint32_t aoff = (uint32_t)(ks >> 2) * 16384 +
                sw128((uint32_t)(arow * 128 + ((ks & 3) * 16 + acol8) * 2));
            uint32_t qh0, qh1, qh2, qh3, ql0, ql1, ql2, ql3;
            LDSM_X4(qh0, qh1, qh2, qh3, sQh + aoff);
            LDSM_X4(ql0, ql1, ql2, ql3, sQl + aoff);
#pragma unroll
            for (int ng = 0; ng < 4; ++ng) {
                const uint32_t boff = (uint32_t)(ks >> 2) * 8192 +
                    sw128((uint32_t)((ng * 16 + brow) * 128 + ((ks & 3) * 16 + bcol8) * 2));
                uint32_t kh0, kh1, kh2, kh3, kl0, kl1, kl2, kl3;
                LDSM_X4(kh0, kh1, kh2, kh3, sKh + boff);
                LDSM_X4(kl0, kl1, kl2, kl3, sKl + boff);
                MMA16816(sacc[2 * ng], qh0, qh1, qh2, qh3, kh0, kh1);
                MMA16816(sacc[2 * ng], ql0, ql1, ql2, ql3, kh0, kh1);
                MMA16816(sacc[2 * ng], qh0, qh1, qh2, qh3, kl0, kl1);
                MMA16816(sacc[2 * ng + 1], qh0, qh1, qh2, qh3, kh2, kh3);
                MMA16816(sacc[2 * ng + 1], ql0, ql1, ql2, ql3, kh2, kh3);
                MMA16816(sacc[2 * ng + 1], qh0, qh1, qh2, qh3, kl2, kl3);
            }
        }

        // ---- Causal mask (only last two kv tiles touch the diagonal) ----
        if (kt >= iters - 2) {
            const int rbase = q0 + 16 * wid + (lane >> 2);
#pragma unroll
            for (int nt = 0; nt < 8; ++nt) {
#pragma unroll
                for (int u = 0; u < 4; ++u) {
                    int colg = k0g + 8 * nt + 2 * (lane & 3) + (u & 1);
                    int rowg = rbase + ((u >> 1) << 3);
                    if (colg > rowg) sacc[nt][u] = -1e30f;
                }
            }
        }

        // ---- Online softmax ----
        float alpha[2], mn[2];
#pragma unroll
        for (int hf = 0; hf < 2; ++hf) {
            float mt = -1e30f;
#pragma unroll
            for (int nt = 0; nt < 8; ++nt) {
                mt = fmaxf(mt, sacc[nt][2 * hf]);
                mt = fmaxf(mt, sacc[nt][2 * hf + 1]);
            }
            mt = fmaxf(mt, __shfl_xor_sync(0xffffffffu, mt, 1));
            mt = fmaxf(mt, __shfl_xor_sync(0xffffffffu, mt, 2));
            mn[hf] = fmaxf(mrow[hf], mt);
            alpha[hf] = __expf(mrow[hf] - mn[hf]);
            mrow[hf] = mn[hf];
        }

        uint32_t aPh[4][4], aPl[4][4];
        float rs[2] = { 0.f, 0.f };
#pragma unroll
        for (int nt = 0; nt < 8; ++nt) {
            float p0 = __expf(sacc[nt][0] - mn[0]);
            float p1 = __expf(sacc[nt][1] - mn[0]);
            float p2 = __expf(sacc[nt][2] - mn[1]);
            float p3 = __expf(sacc[nt][3] - mn[1]);
            rs[0] += p0 + p1;
            rs[1] += p2 + p3;
            float h0 = __bfloat162float(__float2bfloat16(p0));
            float h1 = __bfloat162float(__float2bfloat16(p1));
            float h2 = __bfloat162float(__float2bfloat16(p2));
            float h3 = __bfloat162float(__float2bfloat16(p3));
            int kk = nt >> 1;
            int od = (nt & 1) * 2;
            aPh[kk][od + 0] = pack_bf16(h0, h1);
            aPh[kk][od + 1] = pack_bf16(h2, h3);
            aPl[kk][od + 0] = pack_bf16(p0 - h0, p1 - h1);
            aPl[kk][od + 1] = pack_bf16(p2 - h2, p3 - h3);
        }
#pragma unroll
        for (int hf = 0; hf < 2; ++hf) {
            rs[hf] += __shfl_xor_sync(0xffffffffu, rs[hf], 1);
            rs[hf] += __shfl_xor_sync(0xffffffffu, rs[hf], 2);
            lrow[hf] = lrow[hf] * alpha[hf] + rs[hf];
        }
#pragma unroll
        for (int nt = 0; nt < 16; ++nt) {
            oacc[nt][0] *= alpha[0];
            oacc[nt][1] *= alpha[0];
            oacc[nt][2] *= alpha[1];
            oacc[nt][3] *= alpha[1];
        }

        // ---- O += P V (split, 3 products) ----
#pragma unroll
        for (int kk = 0; kk < 4; ++kk) {
#pragma unroll
            for (int ng = 0; ng < 8; ++ng) {
                int vcol = ng * 16 + vcol8;
                uint32_t voff = (uint32_t)(vcol >> 6) * 8192 +
                    sw128((uint32_t)((kk * 16 + vrow16) * 128 + (vcol & 63) * 2));
                uint32_t vh0, vh1, vh2, vh3, vl0, vl1, vl2, vl3;
                LDSM_X4_T(vh0, vh1, vh2, vh3, sVh + voff);
                LDSM_X4_T(vl0, vl1, vl2, vl3, sVl + voff);
                MMA16816(oacc[2 * ng], aPh[kk][0], aPh[kk][1], aPh[kk][2], aPh[kk][3], vh0, vh1);
                MMA16816(oacc[2 * ng], aPl[kk][0], aPl[kk][1], aPl[kk][2], aPl[kk][3], vh0, vh1);
                MMA16816(oacc[2 * ng], aPh[kk][0], aPh[kk][1], aPh[kk][2], aPh[kk][3], vl0, vl1);
                MMA16816(oacc[2 * ng + 1], aPh[kk][0], aPh[kk][1], aPh[kk][2], aPh[kk][3], vh2, vh3);
                MMA16816(oacc[2 * ng + 1], aPl[kk][0], aPl[kk][1], aPl[kk][2], aPl[kk][3], vh2, vh3);
                MMA16816(oacc[2 * ng + 1], aPh[kk][0], aPh[kk][1], aPh[kk][2], aPh[kk][3], vl2, vl3);
            }
        }
    }

    // ---- Epilogue ----
    const float inv0 = 1.0f / lrow[0];
    const float inv1 = 1.0f / lrow[1];
    const int r = q0 + 16 * wid + (lane >> 2);
    const int cbase = 2 * (lane & 3);
#pragma unroll
    for (int nt = 0; nt < 16; ++nt) {
        int col = 8 * nt + cbase;
        *(float2*)(O + bOff + (size_t)r * DD + hOff + col) =
            make_float2(oacc[nt][0] * inv0, oacc[nt][1] * inv0);
        *(float2*)(O + bOff + (size_t)(r + 8) * DD + hOff + col) =
            make_float2(oacc[nt][2] * inv1, oacc[nt][3] * inv1);
    }
}

// ---------------------------------------------------------------------------
// Launch
// ---------------------------------------------------------------------------
extern "C" void kernel_launch(void* const* d_in, const int* in_sizes, int n_in,
                              void* d_out, int out_size) {
    const float* x  = (const float*)d_in[0];
    const float* Wq = (const float*)d_in[1];
    const float* Wk = (const float*)d_in[2];
    const float* Wv = (const float*)d_in[3];
    const float* Wo = (const float*)d_in[4];
    float* out = (float*)d_out;

    float *q, *k, *v, *attn;
    __nv_bfloat16 *a3, *b3;
    cudaGetSymbolAddress((void**)&q, g_q);
    cudaGetSymbolAddress((void**)&k, g_k);
    cudaGetSymbolAddress((void**)&v, g_v);
    cudaGetSymbolAddress((void**)&attn, g_attn);
    cudaGetSymbolAddress((void**)&a3, g_a3);
    cudaGetSymbolAddress((void**)&b3, g_b3);

    cudaFuncSetAttribute(gemm_hmma, cudaFuncAttributeMaxDynamicSharedMemorySize, HSMEM);
    cudaFuncSetAttribute(flash_hmma, cudaFuncAttributeMaxDynamicSharedMemorySize, FL_SMEM);

    // 1. RoPE tables
    rope_tables_kernel<<<LL, 64>>>();

    // 2. Split x once (shared by Q/K/V projections)
    split_x_kernel<<<(unsigned)(((size_t)MM * 1024) / 256), 256>>>(x, a3);

    dim3 wGrid(64, 64);
    dim3 wBlk(32, 8);
    dim3 gGrid(DD / 128, MM / 128);

    // 3. QKV projections (HMMA)
    split_w_kernel<<<wGrid, wBlk>>>(Wq, b3);
    gemm_hmma<<<gGrid, 256, HSMEM>>>(a3, b3, q);
    split_w_kernel<<<wGrid, wBlk>>>(Wk, b3);
    gemm_hmma<<<gGrid, 256, HSMEM>>>(a3, b3, k);
    split_w_kernel<<<wGrid, wBlk>>>(Wv, b3);
    gemm_hmma<<<gGrid, 256, HSMEM>>>(a3, b3, v);

    // 4. RoPE on Q and K
    {
        size_t n2 = 2ull * BB * LL * HH * 64;
        rope_apply_kernel<<<(unsigned)(n2 / 256), 256>>>(q, k);
    }

    // 5. Flash attention (HMMA, causal)
    dim3 faGrid(LL / 128, BB * HH);   // (16, 64)
    flash_hmma<<<faGrid, 256, FL_SMEM>>>(q, k, v, attn);

    // 6. Output projection
    split_x_kernel<<<(unsigned)(((size_t)MM * 1024) / 256), 256>>>(attn, a3);
    split_w_kernel<<<wGrid, wBlk>>>(Wo, b3);
    gemm_hmma<<<gGrid, 256, HSMEM>>>(a3, b3, out);
}